// round 7
// baseline (speedup 1.0000x reference)
#include <cuda_runtime.h>
#include <cuda_fp16.h>
#include <cstdint>

// ============================================================================
// LocationAwareAttention  B=32, S=2048, D=512   (family-common PTX only:
// mma.sync.m16n8k16.f16 + ldmatrix + cp.async — NO tcgen05, target is sm_103)
//
// R7: scores reverted to the proven R4 config (M=64 x N=512, 8 warps,
// 3-stage B ring — 149us, at the legacy-HMMA throughput ceiling ~230TF/s).
// Periphery optimized: coalesced smem-tile transpose for w_v fused with qw
// (one 128-block launch), fused softmax+context (no atomics, no zeroing).
// Output: d_out = [ctx (B*D) | align (B*S)] fp32
// ============================================================================

#define BB 32
#define SS 2048
#define DD 512

__device__ __half g_wvt[DD * DD];     // w_v^T [n][k] fp16
__device__ float  g_qw[BB * DD];      // q@w_q + bias + conv_b
__device__ float  g_scores[BB * SS];

// ---------------- SMEM layout (bytes) ----------------
#define SM_B0   0                      // B tile: 3 stages x (512n x 64k fp16=64KB)
#define SM_BSZ  65536
#define SM_A0   196608                 // A: 2 stages x (64 x 64 fp16 = 8KB)
#define SM_A1   204800
#define SM_QWB  212992                 // 512 f32
#define SM_CW0  (SM_QWB + 2048)
#define SM_CW1  (SM_CW0 + 2048)
#define SM_CW2  (SM_CW1 + 2048)
#define SM_SW   (SM_CW2 + 2048)
#define SM_E0   (SM_SW + 2048)         // 64 f32
#define SM_E1   (SM_E0 + 256)
#define SM_E2   (SM_E1 + 256)
#define SM_RED  (SM_E2 + 256)          // 64 x 8 f32
#define SM_TOT  (SM_RED + 2048)        // 226048 B

// ---------------- PTX helpers ----------------
__device__ __forceinline__ uint32_t s2u(const void* p) {
    uint32_t a;
    asm("{ .reg .u64 t; cvta.to.shared.u64 t, %1; cvt.u32.u64 %0, t; }"
        : "=r"(a) : "l"(p));
    return a;
}
__device__ __forceinline__ void cp16(uint32_t dst, const void* src) {
    asm volatile("cp.async.ca.shared.global [%0], [%1], 16;"
                 :: "r"(dst), "l"(src) : "memory");
}
__device__ __forceinline__ void cp_commit() {
    asm volatile("cp.async.commit_group;" ::: "memory");
}
__device__ __forceinline__ void cp_wait0() {
    asm volatile("cp.async.wait_group 0;" ::: "memory");
}
__device__ __forceinline__ void cp_wait1() {
    asm volatile("cp.async.wait_group 1;" ::: "memory");
}
__device__ __forceinline__ void ldsm4(uint32_t& r0, uint32_t& r1,
                                      uint32_t& r2, uint32_t& r3, uint32_t a) {
    asm volatile("ldmatrix.sync.aligned.m8n8.x4.shared.b16 {%0,%1,%2,%3}, [%4];"
                 : "=r"(r0), "=r"(r1), "=r"(r2), "=r"(r3) : "r"(a));
}
__device__ __forceinline__ void mma16816(float* d, const uint32_t* a,
                                         const uint32_t* b) {
    asm volatile(
        "mma.sync.aligned.m16n8k16.row.col.f32.f16.f16.f32 "
        "{%0,%1,%2,%3}, {%4,%5,%6,%7}, {%8,%9}, {%0,%1,%2,%3};"
        : "+f"(d[0]), "+f"(d[1]), "+f"(d[2]), "+f"(d[3])
        : "r"(a[0]), "r"(a[1]), "r"(a[2]), "r"(a[3]), "r"(b[0]), "r"(b[1]));
}
__device__ __forceinline__ uint32_t packh(__half a, __half b) {
    __half2 h2; h2.x = a; h2.y = b;
    return *(uint32_t*)&h2;
}
__device__ __forceinline__ uint32_t swz(uint32_t row, uint32_t colByte) {
    return row * 128u + (colByte ^ ((row & 7u) << 4));
}

// ============================================================================
// prep: one launch, 128 blocks.
//   blocks [0,64):   w_v^T -> fp16 via coalesced 64x64 smem-tile transpose
//   blocks [64,128): g_qw[b, dhalf] = q@w_q + bias + conv_b
// ============================================================================
__global__ void __launch_bounds__(256)
prep_kernel(const float* __restrict__ w_v,
            const float* __restrict__ query,
            const float* __restrict__ w_q,
            const float* __restrict__ bias,
            const float* __restrict__ conv_b) {
    const int blk = blockIdx.x, tid = threadIdx.x;
    if (blk < 64) {
        __shared__ float tile[64][65];
        const int ti = blk >> 3, tj = blk & 7;   // k-tile, n-tile
        // coalesced read: w_v[k][n], rows of the 64x64 tile as float4
#pragma unroll
        for (int q = 0; q < 4; ++q) {
            int idx = q * 256 + tid;             // float4 slot
            int r = idx >> 4, c4 = idx & 15;
            float4 v = *(const float4*)(w_v + (size_t)(ti * 64 + r) * DD
                                        + tj * 64 + c4 * 4);
            tile[r][c4 * 4 + 0] = v.x;
            tile[r][c4 * 4 + 1] = v.y;
            tile[r][c4 * 4 + 2] = v.z;
            tile[r][c4 * 4 + 3] = v.w;
        }
        __syncthreads();
        // coalesced write: g_wvt[n][k] as half2
#pragma unroll
        for (int q = 0; q < 8; ++q) {
            int slot = q * 256 + tid;            // half2 slot
            int nr = slot >> 5, kc = slot & 31;
            __half2 h = __floats2half2_rn(tile[kc * 2][nr],
                                          tile[kc * 2 + 1][nr]);
            *(__half2*)(g_wvt + (size_t)(tj * 64 + nr) * DD + ti * 64 + kc * 2) = h;
        }
    } else {
        __shared__ float qs[DD];
        const int bb = blk - 64;
        const int b = bb >> 1, dh = bb & 1;
        const int d = dh * 256 + tid;
        qs[tid]       = query[b * DD + tid];
        qs[tid + 256] = query[b * DD + tid + 256];
        __syncthreads();
        float a0 = 0.f, a1 = 0.f, a2 = 0.f, a3 = 0.f;
        float a4 = 0.f, a5 = 0.f, a6 = 0.f, a7 = 0.f;
#pragma unroll 8
        for (int k = 0; k < DD; k += 8) {
            a0 = fmaf(qs[k],     w_q[(k)     * DD + d], a0);
            a1 = fmaf(qs[k + 1], w_q[(k + 1) * DD + d], a1);
            a2 = fmaf(qs[k + 2], w_q[(k + 2) * DD + d], a2);
            a3 = fmaf(qs[k + 3], w_q[(k + 3) * DD + d], a3);
            a4 = fmaf(qs[k + 4], w_q[(k + 4) * DD + d], a4);
            a5 = fmaf(qs[k + 5], w_q[(k + 5) * DD + d], a5);
            a6 = fmaf(qs[k + 6], w_q[(k + 6) * DD + d], a6);
            a7 = fmaf(qs[k + 7], w_q[(k + 7) * DD + d], a7);
        }
        g_qw[b * DD + d] = bias[d] + conv_b[d]
                         + ((a0 + a1) + (a2 + a3)) + ((a4 + a5) + (a6 + a7));
    }
}

// ============================================================================
// scores: per block M=64 rows x N=512 (full D), K=512, single fp16 pass.
// Grid: 1024 blocks (b*32 + tile), 256 threads (8 warps, warp tile 64x64).
// R4-proven config: 3-stage B ring, 2-stage A, B 2 chunks ahead.
// ============================================================================
__global__ void __launch_bounds__(256, 1)
scores_kernel(const float* __restrict__ value,
              const float* __restrict__ energy,
              const float* __restrict__ conv_w,
              const float* __restrict__ score_w) {
    extern __shared__ char smem[];
    const uint32_t sb = s2u(smem);
    const int tid = threadIdx.x, wid = tid >> 5, lid = tid & 31;
    const int b = blockIdx.x >> 5, tile = blockIdx.x & 31;
    const int s0 = tile * 64;
    const size_t grow0 = (size_t)b * SS + s0;

    // ---- epilogue constants ----
    float* c_qwb = (float*)(smem + SM_QWB);
    float* c_cw0 = (float*)(smem + SM_CW0);
    float* c_cw1 = (float*)(smem + SM_CW1);
    float* c_cw2 = (float*)(smem + SM_CW2);
    float* c_sw  = (float*)(smem + SM_SW);
    for (int d = tid; d < DD; d += 256) {
        c_qwb[d] = g_qw[b * DD + d];
        c_cw0[d] = conv_w[d * 3 + 0];
        c_cw1[d] = conv_w[d * 3 + 1];
        c_cw2[d] = conv_w[d * 3 + 2];
        c_sw[d]  = score_w[d];
    }
    if (tid < 64) {
        int s = s0 + tid, gs = b * SS + s;
        ((float*)(smem + SM_E1))[tid] = energy[gs];
        ((float*)(smem + SM_E0))[tid] = (s > 0)      ? energy[gs - 1] : 0.f;
        ((float*)(smem + SM_E2))[tid] = (s < SS - 1) ? energy[gs + 1] : 0.f;
    }

    float4 pre[4];  // prefetched A fp32 (2 tasks x 8 floats)

    auto ldA = [&](int ch) {
        int kb = ch * 64;
#pragma unroll
        for (int q = 0; q < 2; ++q) {
            int t = tid * 2 + q, r = t >> 3, c = t & 7;
            const float4* src =
                (const float4*)(value + (grow0 + r) * DD + kb + c * 8);
            pre[q * 2]     = src[0];
            pre[q * 2 + 1] = src[1];
        }
    };
    auto stsA = [&](int ch) {
        char* ah = smem + ((ch & 1) ? SM_A1 : SM_A0);
#pragma unroll
        for (int q = 0; q < 2; ++q) {
            int t = tid * 2 + q, r = t >> 3, c = t & 7;
            uint32_t off = swz((uint32_t)r, (uint32_t)c * 16);
            uint32_t hh[4];
#pragma unroll
            for (int j = 0; j < 2; ++j) {
                float4 v = pre[q * 2 + j];
                hh[j * 2]     = packh(__float2half_rn(v.x), __float2half_rn(v.y));
                hh[j * 2 + 1] = packh(__float2half_rn(v.z), __float2half_rn(v.w));
            }
            *(uint4*)(ah + off) = make_uint4(hh[0], hh[1], hh[2], hh[3]);
        }
    };
    auto cpB = [&](int ch) {
        int kb = ch * 64;
        uint32_t bbuf = sb + SM_B0 + (uint32_t)(ch % 3) * SM_BSZ;
#pragma unroll
        for (int q = 0; q < 16; ++q) {
            int t = tid + q * 256, n = t >> 3, c = t & 7;
            cp16(bbuf + swz((uint32_t)n, (uint32_t)c * 16),
                 g_wvt + n * DD + kb + c * 8);
        }
        cp_commit();
    };

    float acc[4][8][4];
#pragma unroll
    for (int i = 0; i < 4; ++i)
#pragma unroll
        for (int j = 0; j < 8; ++j)
#pragma unroll
            for (int c = 0; c < 4; ++c) acc[i][j][c] = 0.f;

    const int nwb = wid * 64;

    auto compute = [&](int ch) {
        uint32_t abh = sb + ((ch & 1) ? SM_A1 : SM_A0);
        uint32_t bb  = sb + SM_B0 + (uint32_t)(ch % 3) * SM_BSZ;
#pragma unroll
        for (int s = 0; s < 4; ++s) {
            uint32_t bfr[8][2];
#pragma unroll
            for (int np = 0; np < 4; ++np) {
                uint32_t row = nwb + np * 16 + ((lid & 16) >> 1) + (lid & 7);
                uint32_t col = s * 32 + ((lid & 8) << 1);
                ldsm4(bfr[np * 2][0], bfr[np * 2][1],
                      bfr[np * 2 + 1][0], bfr[np * 2 + 1][1],
                      bb + swz(row, col));
            }
#pragma unroll
            for (int mi = 0; mi < 4; ++mi) {
                uint32_t row = mi * 16 + (lid & 15);
                uint32_t col = s * 32 + (lid & 16);
                uint32_t ah[4];
                ldsm4(ah[0], ah[1], ah[2], ah[3], abh + swz(row, col));
#pragma unroll
                for (int ni = 0; ni < 8; ++ni)
                    mma16816(acc[mi][ni], ah, bfr[ni]);
            }
        }
    };

    // ---- pipelined K loop (8 chunks of 64, B 2 chunks ahead) ----
    ldA(0);
    cpB(0);
    stsA(0);
    cpB(1);
    ldA(1);
    for (int ch = 0; ch < 8; ++ch) {
        if (ch < 7) cp_wait1();
        else        cp_wait0();
        __syncthreads();
        if (ch < 6) cpB(ch + 2);
        if (ch < 7) stsA(ch + 1);
        if (ch < 6) ldA(ch + 2);
        compute(ch);
    }

    // ---- epilogue ----
    const float* E0 = (const float*)(smem + SM_E0);
    const float* E1 = (const float*)(smem + SM_E1);
    const float* E2 = (const float*)(smem + SM_E2);
    float e0r[8], e1r[8], e2r[8];
#pragma unroll
    for (int mi = 0; mi < 4; ++mi)
#pragma unroll
        for (int h = 0; h < 2; ++h) {
            int r = mi * 16 + h * 8 + (lid >> 2);
            e0r[mi * 2 + h] = E0[r];
            e1r[mi * 2 + h] = E1[r];
            e2r[mi * 2 + h] = E2[r];
        }
    float part[8];
#pragma unroll
    for (int i = 0; i < 8; ++i) part[i] = 0.f;

#pragma unroll
    for (int ni = 0; ni < 8; ++ni) {
        int d0 = nwb + ni * 8 + 2 * (lid & 3);
        float qb0 = c_qwb[d0], qb1 = c_qwb[d0 + 1];
        float w00 = c_cw0[d0], w01 = c_cw0[d0 + 1];
        float w10 = c_cw1[d0], w11 = c_cw1[d0 + 1];
        float w20 = c_cw2[d0], w21 = c_cw2[d0 + 1];
        float sw0 = c_sw[d0],  sw1 = c_sw[d0 + 1];
#pragma unroll
        for (int mi = 0; mi < 4; ++mi)
#pragma unroll
            for (int h = 0; h < 2; ++h) {
                int pi = mi * 2 + h;
                float x0 = acc[mi][ni][h * 2] + qb0
                         + e0r[pi] * w00 + e1r[pi] * w10 + e2r[pi] * w20;
                float x1 = acc[mi][ni][h * 2 + 1] + qb1
                         + e0r[pi] * w01 + e1r[pi] * w11 + e2r[pi] * w21;
                float t0 = 1.f - __fdividef(2.f, __expf(2.f * x0) + 1.f);
                float t1 = 1.f - __fdividef(2.f, __expf(2.f * x1) + 1.f);
                part[pi] = fmaf(t0, sw0, fmaf(t1, sw1, part[pi]));
            }
    }
#pragma unroll
    for (int pi = 0; pi < 8; ++pi) {
        part[pi] += __shfl_xor_sync(0xffffffffu, part[pi], 1);
        part[pi] += __shfl_xor_sync(0xffffffffu, part[pi], 2);
    }
    float* red = (float*)(smem + SM_RED);
    if ((lid & 3) == 0) {
#pragma unroll
        for (int mi = 0; mi < 4; ++mi)
#pragma unroll
            for (int h = 0; h < 2; ++h) {
                int r = mi * 16 + h * 8 + (lid >> 2);
                red[r * 8 + wid] = part[mi * 2 + h];
            }
    }
    __syncthreads();
    if (tid < 64) {
        float sum = 0.f;   // score_b dropped: softmax is shift-invariant
#pragma unroll
        for (int w = 0; w < 8; ++w) sum += red[tid * 8 + w];
        g_scores[b * SS + s0 + tid] = sum;
    }
}

// ============================================================================
// softmax + context fused. Grid (32, 4): b, dch (128 d-cols each).
// ============================================================================
__global__ void __launch_bounds__(256)
softmax_context_kernel(const float* __restrict__ value,
                       float* __restrict__ align_out,
                       float* __restrict__ ctx_out) {
    __shared__ float sc[SS];
    __shared__ float wred[8];
    __shared__ float pc[256];
    const int b = blockIdx.x, dch = blockIdx.y;
    const int t = threadIdx.x, w = t >> 5, l = t & 31;

    float v[8];
#pragma unroll
    for (int j = 0; j < 8; ++j) v[j] = g_scores[b * SS + t + j * 256];
    float m = v[0];
#pragma unroll
    for (int j = 1; j < 8; ++j) m = fmaxf(m, v[j]);
#pragma unroll
    for (int o = 16; o > 0; o >>= 1)
        m = fmaxf(m, __shfl_xor_sync(0xffffffffu, m, o));
    if (l == 0) wred[w] = m;
    __syncthreads();
    m = wred[0];
#pragma unroll
    for (int i = 1; i < 8; ++i) m = fmaxf(m, wred[i]);
    __syncthreads();

    float e[8], sum = 0.f;
#pragma unroll
    for (int j = 0; j < 8; ++j) { e[j] = __expf(v[j] - m); sum += e[j]; }
#pragma unroll
    for (int o = 16; o > 0; o >>= 1)
        sum += __shfl_xor_sync(0xffffffffu, sum, o);
    if (l == 0) wred[w] = sum;
    __syncthreads();
    sum = wred[0];
#pragma unroll
    for (int i = 1; i < 8; ++i) sum += wred[i];
    float inv = 1.f / sum;
#pragma unroll
    for (int j = 0; j < 8; ++j) {
        float a = e[j] * inv;
        sc[t + j * 256] = a;
        if (dch == 0) align_out[b * SS + t + j * 256] = a;
    }
    __syncthreads();

    const int col = dch * 128 + (t & 127);
    const int sh = t >> 7;
    const float* vb = value + ((size_t)b * SS + sh * 1024) * DD + col;
    const float* ab = sc + sh * 1024;
    float a0 = 0.f, a1 = 0.f;
#pragma unroll 4
    for (int s = 0; s < 1024; s += 2) {
        a0 = fmaf(ab[s],     vb[(size_t)s * DD],       a0);
        a1 = fmaf(ab[s + 1], vb[(size_t)(s + 1) * DD], a1);
    }
    pc[t] = a0 + a1;
    __syncthreads();
    if (t < 128) ctx_out[b * DD + dch * 128 + t] = pc[t] + pc[t + 128];
}

// ============================================================================
// launch
// ============================================================================
extern "C" void kernel_launch(void* const* d_in, const int* in_sizes, int n_in,
                              void* d_out, int out_size) {
    const float* query   = (const float*)d_in[0];
    const float* value   = (const float*)d_in[1];
    const float* energy  = (const float*)d_in[2];
    const float* conv_w  = (const float*)d_in[3];
    const float* conv_b  = (const float*)d_in[4];
    const float* w_q     = (const float*)d_in[5];
    const float* w_v     = (const float*)d_in[6];
    const float* bias    = (const float*)d_in[7];
    const float* score_w = (const float*)d_in[8];
    float* out_ctx   = (float*)d_out;            // [B*D]
    float* out_align = (float*)d_out + BB * DD;  // [B*S]

    cudaFuncSetAttribute(scores_kernel,
                         cudaFuncAttributeMaxDynamicSharedMemorySize, SM_TOT);

    prep_kernel<<<128, 256>>>(w_v, query, w_q, bias, conv_b);
    scores_kernel<<<BB * 32, 256, SM_TOT>>>(value, energy, conv_w, score_w);
    softmax_context_kernel<<<dim3(BB, 4), 256>>>(value, out_align, out_ctx);
}

// round 8
// speedup vs baseline: 1.1477x; 1.1477x over previous
#include <cuda_runtime.h>
#include <cuda_fp16.h>
#include <cstdint>

// ============================================================================
// LocationAwareAttention  B=32, S=2048, D=512   (family-common PTX only:
// mma.sync.m16n8k16.f16 + ldmatrix + cp.async — NO tcgen05, target is sm_103)
//
// R8: A-path removed from scores. value pre-converted to fp16 in gmem
// (streaming prep), scores cp.asyncs A+B per chunk in one group through the
// proven R4 3-stage ring. Loop body = wait/sync/cp/ldsm/mma only.
// Epilogue consts via L2 loads; RED aliases dead stage-0 smem.
// Periphery = fastest measured variants (separate softmax + R4 context).
// Output: d_out = [ctx (B*D) | align (B*S)] fp32
// ============================================================================

#define BB 32
#define SS 2048
#define DD 512

__device__ __align__(16) __half g_wvt[DD * DD];          // w_v^T [n][k] fp16
__device__ __align__(16) __half g_valh[BB * SS * DD];    // value fp16
__device__ float g_qw[BB * DD];                          // q@w_q + bias + conv_b
__device__ float g_scores[BB * SS];

// ---------------- SMEM layout (bytes) ----------------
// 3 stages x [B 64KB | A 8KB] = 221184, then cw0,cw1,cw2,sw (4 x 2048).
#define SM_STG   73728
#define SM_AOFF  65536
#define SM_CW0   221184
#define SM_CW1   (SM_CW0 + 2048)
#define SM_CW2   (SM_CW1 + 2048)
#define SM_SW    (SM_CW2 + 2048)
#define SM_TOT   (SM_SW + 2048)        // 229376 B (< 227KB opt-in cap)
// RED (64 x 8 f32) aliases stage-0 B region after the K loop.

// ---------------- PTX helpers ----------------
__device__ __forceinline__ uint32_t s2u(const void* p) {
    uint32_t a;
    asm("{ .reg .u64 t; cvta.to.shared.u64 t, %1; cvt.u32.u64 %0, t; }"
        : "=r"(a) : "l"(p));
    return a;
}
__device__ __forceinline__ void cp16(uint32_t dst, const void* src) {
    asm volatile("cp.async.ca.shared.global [%0], [%1], 16;"
                 :: "r"(dst), "l"(src) : "memory");
}
__device__ __forceinline__ void cp_commit() {
    asm volatile("cp.async.commit_group;" ::: "memory");
}
__device__ __forceinline__ void cp_wait0() {
    asm volatile("cp.async.wait_group 0;" ::: "memory");
}
__device__ __forceinline__ void cp_wait1() {
    asm volatile("cp.async.wait_group 1;" ::: "memory");
}
__device__ __forceinline__ void ldsm4(uint32_t& r0, uint32_t& r1,
                                      uint32_t& r2, uint32_t& r3, uint32_t a) {
    asm volatile("ldmatrix.sync.aligned.m8n8.x4.shared.b16 {%0,%1,%2,%3}, [%4];"
                 : "=r"(r0), "=r"(r1), "=r"(r2), "=r"(r3) : "r"(a));
}
__device__ __forceinline__ void mma16816(float* d, const uint32_t* a,
                                         const uint32_t* b) {
    asm volatile(
        "mma.sync.aligned.m16n8k16.row.col.f32.f16.f16.f32 "
        "{%0,%1,%2,%3}, {%4,%5,%6,%7}, {%8,%9}, {%0,%1,%2,%3};"
        : "+f"(d[0]), "+f"(d[1]), "+f"(d[2]), "+f"(d[3])
        : "r"(a[0]), "r"(a[1]), "r"(a[2]), "r"(a[3]), "r"(b[0]), "r"(b[1]));
}
__device__ __forceinline__ uint32_t swz(uint32_t row, uint32_t colByte) {
    return row * 128u + (colByte ^ ((row & 7u) << 4));
}

// ============================================================================
// prep_all: one launch, 1152 blocks x 256 threads.
//   [0,1024):     value fp32 -> g_valh fp16 (64 rows per block, streaming)
//   [1024,1088):  w_v^T -> fp16 via coalesced 64x64 smem-tile transpose
//   [1088,1152):  g_qw[b, dhalf] = q@w_q + bias + conv_b
// ============================================================================
__global__ void __launch_bounds__(256)
prep_all_kernel(const float* __restrict__ value,
                const float* __restrict__ w_v,
                const float* __restrict__ query,
                const float* __restrict__ w_q,
                const float* __restrict__ bias,
                const float* __restrict__ conv_b) {
    const int blk = blockIdx.x, tid = threadIdx.x;
    if (blk < 1024) {
        const size_t base = (size_t)blk * 64 * DD;   // 64 rows of 512 floats
        const float4* src = (const float4*)(value + base);
        char* dst = (char*)(g_valh + base);
#pragma unroll
        for (int q = 0; q < 32; ++q) {
            int slot = q * 256 + tid;                // float4 slot, 8192 total
            float4 v = src[slot];
            __half2 h01 = __floats2half2_rn(v.x, v.y);
            __half2 h23 = __floats2half2_rn(v.z, v.w);
            uint2 u;
            u.x = *reinterpret_cast<uint32_t*>(&h01);
            u.y = *reinterpret_cast<uint32_t*>(&h23);
            *(uint2*)(dst + (size_t)slot * 8) = u;
        }
    } else if (blk < 1088) {
        __shared__ float tile[64][65];
        const int bb = blk - 1024;
        const int ti = bb >> 3, tj = bb & 7;         // k-tile, n-tile
#pragma unroll
        for (int q = 0; q < 4; ++q) {
            int idx = q * 256 + tid;
            int r = idx >> 4, c4 = idx & 15;
            float4 v = *(const float4*)(w_v + (size_t)(ti * 64 + r) * DD
                                        + tj * 64 + c4 * 4);
            tile[r][c4 * 4 + 0] = v.x;
            tile[r][c4 * 4 + 1] = v.y;
            tile[r][c4 * 4 + 2] = v.z;
            tile[r][c4 * 4 + 3] = v.w;
        }
        __syncthreads();
#pragma unroll
        for (int q = 0; q < 8; ++q) {
            int slot = q * 256 + tid;
            int nr = slot >> 5, kc = slot & 31;
            __half2 h = __floats2half2_rn(tile[kc * 2][nr],
                                          tile[kc * 2 + 1][nr]);
            *(__half2*)(g_wvt + (size_t)(tj * 64 + nr) * DD + ti * 64 + kc * 2) = h;
        }
    } else {
        __shared__ float qs[DD];
        const int bb = blk - 1088;
        const int b = bb >> 1, dh = bb & 1;
        const int d = dh * 256 + tid;
        qs[tid]       = query[b * DD + tid];
        qs[tid + 256] = query[b * DD + tid + 256];
        __syncthreads();
        float a0 = 0.f, a1 = 0.f, a2 = 0.f, a3 = 0.f;
        float a4 = 0.f, a5 = 0.f, a6 = 0.f, a7 = 0.f;
#pragma unroll 8
        for (int k = 0; k < DD; k += 8) {
            a0 = fmaf(qs[k],     w_q[(k)     * DD + d], a0);
            a1 = fmaf(qs[k + 1], w_q[(k + 1) * DD + d], a1);
            a2 = fmaf(qs[k + 2], w_q[(k + 2) * DD + d], a2);
            a3 = fmaf(qs[k + 3], w_q[(k + 3) * DD + d], a3);
            a4 = fmaf(qs[k + 4], w_q[(k + 4) * DD + d], a4);
            a5 = fmaf(qs[k + 5], w_q[(k + 5) * DD + d], a5);
            a6 = fmaf(qs[k + 6], w_q[(k + 6) * DD + d], a6);
            a7 = fmaf(qs[k + 7], w_q[(k + 7) * DD + d], a7);
        }
        g_qw[b * DD + d] = bias[d] + conv_b[d]
                         + ((a0 + a1) + (a2 + a3)) + ((a4 + a5) + (a6 + a7));
    }
}

// ============================================================================
// scores: per block M=64 rows x N=512 (full D), K=512, fp16 mma, fp32 accum.
// Grid 1024 (b*32 + tile), 256 threads / 8 warps, warp tile 64x64.
// A AND B both via cp.async (fp16 in gmem), one group per chunk, 3-stage ring.
// ============================================================================
__global__ void __launch_bounds__(256, 1)
scores_kernel(const float* __restrict__ energy,
              const float* __restrict__ conv_w,
              const float* __restrict__ score_w) {
    extern __shared__ char smem[];
    const uint32_t sb = s2u(smem);
    const int tid = threadIdx.x, wid = tid >> 5, lid = tid & 31;
    const int b = blockIdx.x >> 5, tile = blockIdx.x & 31;
    const int s0 = tile * 64;
    const size_t grow0 = (size_t)b * SS + s0;

    // ---- conv/score weights into smem (shared by all blocks, L2-hot) ----
    float* c_cw0 = (float*)(smem + SM_CW0);
    float* c_cw1 = (float*)(smem + SM_CW1);
    float* c_cw2 = (float*)(smem + SM_CW2);
    float* c_sw  = (float*)(smem + SM_SW);
    for (int d = tid; d < DD; d += 256) {
        c_cw0[d] = conv_w[d * 3 + 0];
        c_cw1[d] = conv_w[d * 3 + 1];
        c_cw2[d] = conv_w[d * 3 + 2];
        c_sw[d]  = score_w[d];
    }

    // cp.async one chunk: B (512n x 64k) + A (64m x 64k), one commit group
    auto cpAB = [&](int ch) {
        const int kb = ch * 64;
        const uint32_t stg = sb + (uint32_t)(ch % 3) * SM_STG;
#pragma unroll
        for (int q = 0; q < 16; ++q) {
            int t = tid + q * 256, n = t >> 3, c = t & 7;
            cp16(stg + swz((uint32_t)n, (uint32_t)c * 16),
                 g_wvt + (size_t)n * DD + kb + c * 8);
        }
#pragma unroll
        for (int q = 0; q < 2; ++q) {
            int t = tid * 2 + q, r = t >> 3, c = t & 7;
            cp16(stg + SM_AOFF + swz((uint32_t)r, (uint32_t)c * 16),
                 g_valh + (grow0 + r) * DD + kb + c * 8);
        }
        cp_commit();
    };

    float acc[4][8][4];
#pragma unroll
    for (int i = 0; i < 4; ++i)
#pragma unroll
        for (int j = 0; j < 8; ++j)
#pragma unroll
            for (int c = 0; c < 4; ++c) acc[i][j][c] = 0.f;

    const int nwb = wid * 64;

    auto compute = [&](int ch) {
        const uint32_t stg = sb + (uint32_t)(ch % 3) * SM_STG;
        const uint32_t bbuf = stg;
        const uint32_t abuf = stg + SM_AOFF;
#pragma unroll
        for (int s = 0; s < 4; ++s) {
            uint32_t bfr[8][2];
#pragma unroll
            for (int np = 0; np < 4; ++np) {
                uint32_t row = nwb + np * 16 + ((lid & 16) >> 1) + (lid & 7);
                uint32_t col = s * 32 + ((lid & 8) << 1);
                ldsm4(bfr[np * 2][0], bfr[np * 2][1],
                      bfr[np * 2 + 1][0], bfr[np * 2 + 1][1],
                      bbuf + swz(row, col));
            }
#pragma unroll
            for (int mi = 0; mi < 4; ++mi) {
                uint32_t row = mi * 16 + (lid & 15);
                uint32_t col = s * 32 + (lid & 16);
                uint32_t ah[4];
                ldsm4(ah[0], ah[1], ah[2], ah[3], abuf + swz(row, col));
#pragma unroll
                for (int ni = 0; ni < 8; ++ni)
                    mma16816(acc[mi][ni], ah, bfr[ni]);
            }
        }
    };

    // ---- pipelined K loop (8 chunks of 64, 2 chunks ahead, 3-stage ring) ----
    cpAB(0);
    cpAB(1);
    for (int ch = 0; ch < 8; ++ch) {
        if (ch < 7) cp_wait1();   // group(ch) done; group(ch+1) may fly
        else        cp_wait0();
        __syncthreads();          // all warps past compute(ch-1) -> ring safe
        if (ch < 6) cpAB(ch + 2);
        compute(ch);
    }

    // ---- epilogue: x = acc + qw + conv(e); score += tanh(x)*sw ----
    // energy + qw via direct L2 loads (smem freed for the ring).
    float e0r[8], e1r[8], e2r[8];
#pragma unroll
    for (int mi = 0; mi < 4; ++mi)
#pragma unroll
        for (int h = 0; h < 2; ++h) {
            int r = mi * 16 + h * 8 + (lid >> 2);
            int s = s0 + r, gs = b * SS + s;
            e1r[mi * 2 + h] = __ldg(energy + gs);
            e0r[mi * 2 + h] = (s > 0)      ? __ldg(energy + gs - 1) : 0.f;
            e2r[mi * 2 + h] = (s < SS - 1) ? __ldg(energy + gs + 1) : 0.f;
        }
    float part[8];
#pragma unroll
    for (int i = 0; i < 8; ++i) part[i] = 0.f;

#pragma unroll
    for (int ni = 0; ni < 8; ++ni) {
        int d0 = nwb + ni * 8 + 2 * (lid & 3);
        float qb0 = __ldg(&g_qw[b * DD + d0]);
        float qb1 = __ldg(&g_qw[b * DD + d0 + 1]);
        float w00 = c_cw0[d0], w01 = c_cw0[d0 + 1];
        float w10 = c_cw1[d0], w11 = c_cw1[d0 + 1];
        float w20 = c_cw2[d0], w21 = c_cw2[d0 + 1];
        float sw0 = c_sw[d0],  sw1 = c_sw[d0 + 1];
#pragma unroll
        for (int mi = 0; mi < 4; ++mi)
#pragma unroll
            for (int h = 0; h < 2; ++h) {
                int pi = mi * 2 + h;
                float x0 = acc[mi][ni][h * 2] + qb0
                         + e0r[pi] * w00 + e1r[pi] * w10 + e2r[pi] * w20;
                float x1 = acc[mi][ni][h * 2 + 1] + qb1
                         + e0r[pi] * w01 + e1r[pi] * w11 + e2r[pi] * w21;
                float t0 = 1.f - __fdividef(2.f, __expf(2.f * x0) + 1.f);
                float t1 = 1.f - __fdividef(2.f, __expf(2.f * x1) + 1.f);
                part[pi] = fmaf(t0, sw0, fmaf(t1, sw1, part[pi]));
            }
    }
#pragma unroll
    for (int pi = 0; pi < 8; ++pi) {
        part[pi] += __shfl_xor_sync(0xffffffffu, part[pi], 1);
        part[pi] += __shfl_xor_sync(0xffffffffu, part[pi], 2);
    }
    float* red = (float*)smem;   // alias dead stage-0 B region
    if ((lid & 3) == 0) {
#pragma unroll
        for (int mi = 0; mi < 4; ++mi)
#pragma unroll
            for (int h = 0; h < 2; ++h) {
                int r = mi * 16 + h * 8 + (lid >> 2);
                red[r * 8 + wid] = part[mi * 2 + h];
            }
    }
    __syncthreads();
    if (tid < 64) {
        float sum = 0.f;   // score_b dropped: softmax shift-invariant
#pragma unroll
        for (int w = 0; w < 8; ++w) sum += red[tid * 8 + w];
        g_scores[b * SS + s0 + tid] = sum;
    }
}

// ============================================================================
// softmax per batch -> align  (256 threads, shuffle reduce)
// ============================================================================
__global__ void softmax_kernel(float* __restrict__ align_out) {
    __shared__ float wred[8];
    int b = blockIdx.x, t = threadIdx.x, w = t >> 5, l = t & 31;
    const float4* s4 = (const float4*)(g_scores + b * SS);
    float4 v0 = s4[t];
    float4 v1 = s4[t + 256];
    float m = fmaxf(fmaxf(fmaxf(v0.x, v0.y), fmaxf(v0.z, v0.w)),
                    fmaxf(fmaxf(v1.x, v1.y), fmaxf(v1.z, v1.w)));
#pragma unroll
    for (int o = 16; o > 0; o >>= 1)
        m = fmaxf(m, __shfl_xor_sync(0xffffffffu, m, o));
    if (l == 0) wred[w] = m;
    __syncthreads();
    m = wred[0];
#pragma unroll
    for (int i = 1; i < 8; ++i) m = fmaxf(m, wred[i]);
    __syncthreads();

    float4 e0, e1;
    e0.x = __expf(v0.x - m); e0.y = __expf(v0.y - m);
    e0.z = __expf(v0.z - m); e0.w = __expf(v0.w - m);
    e1.x = __expf(v1.x - m); e1.y = __expf(v1.y - m);
    e1.z = __expf(v1.z - m); e1.w = __expf(v1.w - m);
    float sum = e0.x + e0.y + e0.z + e0.w + e1.x + e1.y + e1.z + e1.w;
#pragma unroll
    for (int o = 16; o > 0; o >>= 1)
        sum += __shfl_xor_sync(0xffffffffu, sum, o);
    if (l == 0) wred[w] = sum;
    __syncthreads();
    sum = wred[0];
#pragma unroll
    for (int i = 1; i < 8; ++i) sum += wred[i];
    float inv = 1.f / sum;
    e0.x *= inv; e0.y *= inv; e0.z *= inv; e0.w *= inv;
    e1.x *= inv; e1.y *= inv; e1.z *= inv; e1.w *= inv;
    float4* a4 = (float4*)(align_out + b * SS);
    a4[t] = e0;
    a4[t + 256] = e1;
}

// ============================================================================
// context: ctx[b,d] = sum_s align[b,s] * value[b,s,d]   (R4-proven)
// ============================================================================
__global__ void zero_ctx_kernel(float* __restrict__ ctx) {
    int i = blockIdx.x * blockDim.x + threadIdx.x;
    if (i < BB * DD) ctx[i] = 0.f;
}
__global__ void context_kernel(const float* __restrict__ value,
                               const float* __restrict__ align,
                               float* __restrict__ ctx) {
    int b = blockIdx.x, dch = blockIdx.y, sch = blockIdx.z;
    int d = dch * 128 + threadIdx.x;
    const float* vb = value + ((size_t)b * SS + sch * 256) * DD + d;
    const float* ab = align + b * SS + sch * 256;
    float acc = 0.f;
#pragma unroll 8
    for (int s = 0; s < 256; ++s)
        acc = fmaf(ab[s], vb[(size_t)s * DD], acc);
    atomicAdd(&ctx[b * DD + d], acc);
}

// ============================================================================
// launch
// ============================================================================
extern "C" void kernel_launch(void* const* d_in, const int* in_sizes, int n_in,
                              void* d_out, int out_size) {
    const float* query   = (const float*)d_in[0];
    const float* value   = (const float*)d_in[1];
    const float* energy  = (const float*)d_in[2];
    const float* conv_w  = (const float*)d_in[3];
    const float* conv_b  = (const float*)d_in[4];
    const float* w_q     = (const float*)d_in[5];
    const float* w_v     = (const float*)d_in[6];
    const float* bias    = (const float*)d_in[7];
    const float* score_w = (const float*)d_in[8];
    float* out_ctx   = (float*)d_out;            // [B*D]
    float* out_align = (float*)d_out + BB * DD;  // [B*S]

    cudaFuncSetAttribute(scores_kernel,
                         cudaFuncAttributeMaxDynamicSharedMemorySize, SM_TOT);

    zero_ctx_kernel<<<(BB * DD + 255) / 256, 256>>>(out_ctx);
    prep_all_kernel<<<1152, 256>>>(value, w_v, query, w_q, bias, conv_b);
    scores_kernel<<<BB * 32, 256, SM_TOT>>>(energy, conv_w, score_w);
    softmax_kernel<<<BB, 256>>>(out_align);
    context_kernel<<<dim3(BB, DD / 128, SS / 256), 128>>>(value, out_align,
                                                          out_ctx);
}

// round 9
// speedup vs baseline: 1.3911x; 1.2121x over previous
#include <cuda_runtime.h>
#include <cuda_fp16.h>
#include <cstdint>

// ============================================================================
// LocationAwareAttention  B=32, S=2048, D=512   (family-common PTX only:
// mma.sync.m16n8k16.f16 + ldmatrix + cp.async — NO tcgen05, target is sm_103)
//
// R9: scores = R4-proven config (149us, at legacy mma.sync ceiling ~230TF/s;
// R5/R6/R8 proved it insensitive to warps/CTAs/A-path). Periphery compressed:
// qw GEMV was latency-bound (~28us) -> 8-way k-split + atomicAdd (~3us);
// coalesced w_v transpose; proven softmax + context.
// Output: d_out = [ctx (B*D) | align (B*S)] fp32
// ============================================================================

#define BB 32
#define SS 2048
#define DD 512

__device__ __half g_wvt[DD * DD];     // w_v^T [n][k] fp16
__device__ float  g_qw[BB * DD];      // q@w_q + bias + conv_b  (atomic-built)
__device__ float  g_scores[BB * SS];

// ---------------- SMEM layout (bytes) ----------------
#define SM_B0   0                      // B tile: 3 stages x (512n x 64k fp16=64KB)
#define SM_BSZ  65536
#define SM_A0   196608                 // A: 2 stages x (64 x 64 fp16 = 8KB)
#define SM_A1   204800
#define SM_QWB  212992                 // 512 f32
#define SM_CW0  (SM_QWB + 2048)
#define SM_CW1  (SM_CW0 + 2048)
#define SM_CW2  (SM_CW1 + 2048)
#define SM_SW   (SM_CW2 + 2048)
#define SM_E0   (SM_SW + 2048)         // 64 f32
#define SM_E1   (SM_E0 + 256)
#define SM_E2   (SM_E1 + 256)
#define SM_RED  (SM_E2 + 256)          // 64 x 8 f32
#define SM_TOT  (SM_RED + 2048)        // 226048 B

// ---------------- PTX helpers ----------------
__device__ __forceinline__ uint32_t s2u(const void* p) {
    uint32_t a;
    asm("{ .reg .u64 t; cvta.to.shared.u64 t, %1; cvt.u32.u64 %0, t; }"
        : "=r"(a) : "l"(p));
    return a;
}
__device__ __forceinline__ void cp16(uint32_t dst, const void* src) {
    asm volatile("cp.async.ca.shared.global [%0], [%1], 16;"
                 :: "r"(dst), "l"(src) : "memory");
}
__device__ __forceinline__ void cp_commit() {
    asm volatile("cp.async.commit_group;" ::: "memory");
}
__device__ __forceinline__ void cp_wait0() {
    asm volatile("cp.async.wait_group 0;" ::: "memory");
}
__device__ __forceinline__ void cp_wait1() {
    asm volatile("cp.async.wait_group 1;" ::: "memory");
}
__device__ __forceinline__ void ldsm4(uint32_t& r0, uint32_t& r1,
                                      uint32_t& r2, uint32_t& r3, uint32_t a) {
    asm volatile("ldmatrix.sync.aligned.m8n8.x4.shared.b16 {%0,%1,%2,%3}, [%4];"
                 : "=r"(r0), "=r"(r1), "=r"(r2), "=r"(r3) : "r"(a));
}
__device__ __forceinline__ void mma16816(float* d, const uint32_t* a,
                                         const uint32_t* b) {
    asm volatile(
        "mma.sync.aligned.m16n8k16.row.col.f32.f16.f16.f32 "
        "{%0,%1,%2,%3}, {%4,%5,%6,%7}, {%8,%9}, {%0,%1,%2,%3};"
        : "+f"(d[0]), "+f"(d[1]), "+f"(d[2]), "+f"(d[3])
        : "r"(a[0]), "r"(a[1]), "r"(a[2]), "r"(a[3]), "r"(b[0]), "r"(b[1]));
}
__device__ __forceinline__ uint32_t packh(__half a, __half b) {
    __half2 h2; h2.x = a; h2.y = b;
    return *(uint32_t*)&h2;
}
__device__ __forceinline__ uint32_t swz(uint32_t row, uint32_t colByte) {
    return row * 128u + (colByte ^ ((row & 7u) << 4));
}

// ============================================================================
// zero: g_qw and ctx (both BB*DD) — must precede prep's atomics.
// ============================================================================
__global__ void zero_kernel(float* __restrict__ ctx) {
    int i = blockIdx.x * blockDim.x + threadIdx.x;
    if (i < BB * DD) { ctx[i] = 0.f; g_qw[i] = 0.f; }
}

// ============================================================================
// prep: one launch, 576 blocks x 256 threads.
//   [0,64):   w_v^T -> fp16 via coalesced 64x64 smem-tile transpose
//   [64,576): qw k-split: block (b, dh, ks) accumulates 64 k-iters of
//             q[b]@w_q[:,d] and atomicAdds into g_qw (ks==0 adds bias+conv_b)
// ============================================================================
__global__ void __launch_bounds__(256)
prep_kernel(const float* __restrict__ w_v,
            const float* __restrict__ query,
            const float* __restrict__ w_q,
            const float* __restrict__ bias,
            const float* __restrict__ conv_b) {
    const int blk = blockIdx.x, tid = threadIdx.x;
    if (blk < 64) {
        __shared__ float tile[64][65];
        const int ti = blk >> 3, tj = blk & 7;   // k-tile, n-tile
#pragma unroll
        for (int q = 0; q < 4; ++q) {
            int idx = q * 256 + tid;
            int r = idx >> 4, c4 = idx & 15;
            float4 v = *(const float4*)(w_v + (size_t)(ti * 64 + r) * DD
                                        + tj * 64 + c4 * 4);
            tile[r][c4 * 4 + 0] = v.x;
            tile[r][c4 * 4 + 1] = v.y;
            tile[r][c4 * 4 + 2] = v.z;
            tile[r][c4 * 4 + 3] = v.w;
        }
        __syncthreads();
#pragma unroll
        for (int q = 0; q < 8; ++q) {
            int slot = q * 256 + tid;
            int nr = slot >> 5, kc = slot & 31;
            __half2 h = __floats2half2_rn(tile[kc * 2][nr],
                                          tile[kc * 2 + 1][nr]);
            *(__half2*)(g_wvt + (size_t)(tj * 64 + nr) * DD + ti * 64 + kc * 2) = h;
        }
    } else {
        const int bb = blk - 64;                 // 0..511
        const int ks = bb & 7;                   // k-chunk [ks*64, +64)
        const int dh = (bb >> 3) & 1;
        const int b  = bb >> 4;
        const int d  = dh * 256 + tid;
        const float* q = query + b * DD + ks * 64;
        const float* w = w_q + (size_t)(ks * 64) * DD + d;
        float a0 = 0.f, a1 = 0.f, a2 = 0.f, a3 = 0.f;
        float a4 = 0.f, a5 = 0.f, a6 = 0.f, a7 = 0.f;
#pragma unroll
        for (int k = 0; k < 64; k += 8) {
            a0 = fmaf(__ldg(q + k),     __ldg(w + (size_t)(k)     * DD), a0);
            a1 = fmaf(__ldg(q + k + 1), __ldg(w + (size_t)(k + 1) * DD), a1);
            a2 = fmaf(__ldg(q + k + 2), __ldg(w + (size_t)(k + 2) * DD), a2);
            a3 = fmaf(__ldg(q + k + 3), __ldg(w + (size_t)(k + 3) * DD), a3);
            a4 = fmaf(__ldg(q + k + 4), __ldg(w + (size_t)(k + 4) * DD), a4);
            a5 = fmaf(__ldg(q + k + 5), __ldg(w + (size_t)(k + 5) * DD), a5);
            a6 = fmaf(__ldg(q + k + 6), __ldg(w + (size_t)(k + 6) * DD), a6);
            a7 = fmaf(__ldg(q + k + 7), __ldg(w + (size_t)(k + 7) * DD), a7);
        }
        float sum = ((a0 + a1) + (a2 + a3)) + ((a4 + a5) + (a6 + a7));
        if (ks == 0) sum += bias[d] + conv_b[d];
        atomicAdd(&g_qw[b * DD + d], sum);
    }
}

// ============================================================================
// scores: per block M=64 rows x N=512 (full D), K=512, single fp16 pass.
// Grid: 1024 blocks (b*32 + tile), 256 threads (8 warps, warp tile 64x64).
// R4-proven config: 3-stage B ring, 2-stage A, B 2 chunks ahead. UNCHANGED.
// ============================================================================
__global__ void __launch_bounds__(256, 1)
scores_kernel(const float* __restrict__ value,
              const float* __restrict__ energy,
              const float* __restrict__ conv_w,
              const float* __restrict__ score_w) {
    extern __shared__ char smem[];
    const uint32_t sb = s2u(smem);
    const int tid = threadIdx.x, wid = tid >> 5, lid = tid & 31;
    const int b = blockIdx.x >> 5, tile = blockIdx.x & 31;
    const int s0 = tile * 64;
    const size_t grow0 = (size_t)b * SS + s0;

    // ---- epilogue constants ----
    float* c_qwb = (float*)(smem + SM_QWB);
    float* c_cw0 = (float*)(smem + SM_CW0);
    float* c_cw1 = (float*)(smem + SM_CW1);
    float* c_cw2 = (float*)(smem + SM_CW2);
    float* c_sw  = (float*)(smem + SM_SW);
    for (int d = tid; d < DD; d += 256) {
        c_qwb[d] = g_qw[b * DD + d];
        c_cw0[d] = conv_w[d * 3 + 0];
        c_cw1[d] = conv_w[d * 3 + 1];
        c_cw2[d] = conv_w[d * 3 + 2];
        c_sw[d]  = score_w[d];
    }
    if (tid < 64) {
        int s = s0 + tid, gs = b * SS + s;
        ((float*)(smem + SM_E1))[tid] = energy[gs];
        ((float*)(smem + SM_E0))[tid] = (s > 0)      ? energy[gs - 1] : 0.f;
        ((float*)(smem + SM_E2))[tid] = (s < SS - 1) ? energy[gs + 1] : 0.f;
    }

    float4 pre[4];  // prefetched A fp32 (2 tasks x 8 floats)

    auto ldA = [&](int ch) {
        int kb = ch * 64;
#pragma unroll
        for (int q = 0; q < 2; ++q) {
            int t = tid * 2 + q, r = t >> 3, c = t & 7;
            const float4* src =
                (const float4*)(value + (grow0 + r) * DD + kb + c * 8);
            pre[q * 2]     = src[0];
            pre[q * 2 + 1] = src[1];
        }
    };
    auto stsA = [&](int ch) {
        char* ah = smem + ((ch & 1) ? SM_A1 : SM_A0);
#pragma unroll
        for (int q = 0; q < 2; ++q) {
            int t = tid * 2 + q, r = t >> 3, c = t & 7;
            uint32_t off = swz((uint32_t)r, (uint32_t)c * 16);
            uint32_t hh[4];
#pragma unroll
            for (int j = 0; j < 2; ++j) {
                float4 v = pre[q * 2 + j];
                hh[j * 2]     = packh(__float2half_rn(v.x), __float2half_rn(v.y));
                hh[j * 2 + 1] = packh(__float2half_rn(v.z), __float2half_rn(v.w));
            }
            *(uint4*)(ah + off) = make_uint4(hh[0], hh[1], hh[2], hh[3]);
        }
    };
    auto cpB = [&](int ch) {
        int kb = ch * 64;
        uint32_t bbuf = sb + SM_B0 + (uint32_t)(ch % 3) * SM_BSZ;
#pragma unroll
        for (int q = 0; q < 16; ++q) {
            int t = tid + q * 256, n = t >> 3, c = t & 7;
            cp16(bbuf + swz((uint32_t)n, (uint32_t)c * 16),
                 g_wvt + n * DD + kb + c * 8);
        }
        cp_commit();
    };

    float acc[4][8][4];
#pragma unroll
    for (int i = 0; i < 4; ++i)
#pragma unroll
        for (int j = 0; j < 8; ++j)
#pragma unroll
            for (int c = 0; c < 4; ++c) acc[i][j][c] = 0.f;

    const int nwb = wid * 64;

    auto compute = [&](int ch) {
        uint32_t abh = sb + ((ch & 1) ? SM_A1 : SM_A0);
        uint32_t bb  = sb + SM_B0 + (uint32_t)(ch % 3) * SM_BSZ;
#pragma unroll
        for (int s = 0; s < 4; ++s) {
            uint32_t bfr[8][2];
#pragma unroll
            for (int np = 0; np < 4; ++np) {
                uint32_t row = nwb + np * 16 + ((lid & 16) >> 1) + (lid & 7);
                uint32_t col = s * 32 + ((lid & 8) << 1);
                ldsm4(bfr[np * 2][0], bfr[np * 2][1],
                      bfr[np * 2 + 1][0], bfr[np * 2 + 1][1],
                      bb + swz(row, col));
            }
#pragma unroll
            for (int mi = 0; mi < 4; ++mi) {
                uint32_t row = mi * 16 + (lid & 15);
                uint32_t col = s * 32 + (lid & 16);
                uint32_t ah[4];
                ldsm4(ah[0], ah[1], ah[2], ah[3], abh + swz(row, col));
#pragma unroll
                for (int ni = 0; ni < 8; ++ni)
                    mma16816(acc[mi][ni], ah, bfr[ni]);
            }
        }
    };

    // ---- pipelined K loop (8 chunks of 64, B 2 chunks ahead) ----
    ldA(0);
    cpB(0);
    stsA(0);
    cpB(1);
    ldA(1);
    for (int ch = 0; ch < 8; ++ch) {
        if (ch < 7) cp_wait1();
        else        cp_wait0();
        __syncthreads();
        if (ch < 6) cpB(ch + 2);
        if (ch < 7) stsA(ch + 1);
        if (ch < 6) ldA(ch + 2);
        compute(ch);
    }

    // ---- epilogue ----
    const float* E0 = (const float*)(smem + SM_E0);
    const float* E1 = (const float*)(smem + SM_E1);
    const float* E2 = (const float*)(smem + SM_E2);
    float e0r[8], e1r[8], e2r[8];
#pragma unroll
    for (int mi = 0; mi < 4; ++mi)
#pragma unroll
        for (int h = 0; h < 2; ++h) {
            int r = mi * 16 + h * 8 + (lid >> 2);
            e0r[mi * 2 + h] = E0[r];
            e1r[mi * 2 + h] = E1[r];
            e2r[mi * 2 + h] = E2[r];
        }
    float part[8];
#pragma unroll
    for (int i = 0; i < 8; ++i) part[i] = 0.f;

#pragma unroll
    for (int ni = 0; ni < 8; ++ni) {
        int d0 = nwb + ni * 8 + 2 * (lid & 3);
        float qb0 = c_qwb[d0], qb1 = c_qwb[d0 + 1];
        float w00 = c_cw0[d0], w01 = c_cw0[d0 + 1];
        float w10 = c_cw1[d0], w11 = c_cw1[d0 + 1];
        float w20 = c_cw2[d0], w21 = c_cw2[d0 + 1];
        float sw0 = c_sw[d0],  sw1 = c_sw[d0 + 1];
#pragma unroll
        for (int mi = 0; mi < 4; ++mi)
#pragma unroll
            for (int h = 0; h < 2; ++h) {
                int pi = mi * 2 + h;
                float x0 = acc[mi][ni][h * 2] + qb0
                         + e0r[pi] * w00 + e1r[pi] * w10 + e2r[pi] * w20;
                float x1 = acc[mi][ni][h * 2 + 1] + qb1
                         + e0r[pi] * w01 + e1r[pi] * w11 + e2r[pi] * w21;
                float t0 = 1.f - __fdividef(2.f, __expf(2.f * x0) + 1.f);
                float t1 = 1.f - __fdividef(2.f, __expf(2.f * x1) + 1.f);
                part[pi] = fmaf(t0, sw0, fmaf(t1, sw1, part[pi]));
            }
    }
#pragma unroll
    for (int pi = 0; pi < 8; ++pi) {
        part[pi] += __shfl_xor_sync(0xffffffffu, part[pi], 1);
        part[pi] += __shfl_xor_sync(0xffffffffu, part[pi], 2);
    }
    float* red = (float*)(smem + SM_RED);
    if ((lid & 3) == 0) {
#pragma unroll
        for (int mi = 0; mi < 4; ++mi)
#pragma unroll
            for (int h = 0; h < 2; ++h) {
                int r = mi * 16 + h * 8 + (lid >> 2);
                red[r * 8 + wid] = part[mi * 2 + h];
            }
    }
    __syncthreads();
    if (tid < 64) {
        float sum = 0.f;   // score_b dropped: softmax shift-invariant
#pragma unroll
        for (int w = 0; w < 8; ++w) sum += red[tid * 8 + w];
        g_scores[b * SS + s0 + tid] = sum;
    }
}

// ============================================================================
// softmax per batch -> align  (256 threads, shuffle reduce; proven 5us)
// ============================================================================
__global__ void softmax_kernel(float* __restrict__ align_out) {
    __shared__ float wred[8];
    int b = blockIdx.x, t = threadIdx.x, w = t >> 5, l = t & 31;
    const float4* s4 = (const float4*)(g_scores + b * SS);
    float4 v0 = s4[t];
    float4 v1 = s4[t + 256];
    float m = fmaxf(fmaxf(fmaxf(v0.x, v0.y), fmaxf(v0.z, v0.w)),
                    fmaxf(fmaxf(v1.x, v1.y), fmaxf(v1.z, v1.w)));
#pragma unroll
    for (int o = 16; o > 0; o >>= 1)
        m = fmaxf(m, __shfl_xor_sync(0xffffffffu, m, o));
    if (l == 0) wred[w] = m;
    __syncthreads();
    m = wred[0];
#pragma unroll
    for (int i = 1; i < 8; ++i) m = fmaxf(m, wred[i]);
    __syncthreads();

    float4 e0, e1;
    e0.x = __expf(v0.x - m); e0.y = __expf(v0.y - m);
    e0.z = __expf(v0.z - m); e0.w = __expf(v0.w - m);
    e1.x = __expf(v1.x - m); e1.y = __expf(v1.y - m);
    e1.z = __expf(v1.z - m); e1.w = __expf(v1.w - m);
    float sum = e0.x + e0.y + e0.z + e0.w + e1.x + e1.y + e1.z + e1.w;
#pragma unroll
    for (int o = 16; o > 0; o >>= 1)
        sum += __shfl_xor_sync(0xffffffffu, sum, o);
    if (l == 0) wred[w] = sum;
    __syncthreads();
    sum = wred[0];
#pragma unroll
    for (int i = 1; i < 8; ++i) sum += wred[i];
    float inv = 1.f / sum;
    e0.x *= inv; e0.y *= inv; e0.z *= inv; e0.w *= inv;
    e1.x *= inv; e1.y *= inv; e1.z *= inv; e1.w *= inv;
    float4* a4 = (float4*)(align_out + b * SS);
    a4[t] = e0;
    a4[t + 256] = e1;
}

// ============================================================================
// context: ctx[b,d] = sum_s align[b,s] * value[b,s,d]   (R4-proven)
// ============================================================================
__global__ void context_kernel(const float* __restrict__ value,
                               const float* __restrict__ align,
                               float* __restrict__ ctx) {
    int b = blockIdx.x, dch = blockIdx.y, sch = blockIdx.z;
    int d = dch * 128 + threadIdx.x;
    const float* vb = value + ((size_t)b * SS + sch * 256) * DD + d;
    const float* ab = align + b * SS + sch * 256;
    float acc = 0.f;
#pragma unroll 8
    for (int s = 0; s < 256; ++s)
        acc = fmaf(ab[s], vb[(size_t)s * DD], acc);
    atomicAdd(&ctx[b * DD + d], acc);
}

// ============================================================================
// launch
// ============================================================================
extern "C" void kernel_launch(void* const* d_in, const int* in_sizes, int n_in,
                              void* d_out, int out_size) {
    const float* query   = (const float*)d_in[0];
    const float* value   = (const float*)d_in[1];
    const float* energy  = (const float*)d_in[2];
    const float* conv_w  = (const float*)d_in[3];
    const float* conv_b  = (const float*)d_in[4];
    const float* w_q     = (const float*)d_in[5];
    const float* w_v     = (const float*)d_in[6];
    const float* bias    = (const float*)d_in[7];
    const float* score_w = (const float*)d_in[8];
    float* out_ctx   = (float*)d_out;            // [B*D]
    float* out_align = (float*)d_out + BB * DD;  // [B*S]

    cudaFuncSetAttribute(scores_kernel,
                         cudaFuncAttributeMaxDynamicSharedMemorySize, SM_TOT);

    zero_kernel<<<(BB * DD + 255) / 256, 256>>>(out_ctx);
    prep_kernel<<<576, 256>>>(w_v, query, w_q, bias, conv_b);
    scores_kernel<<<BB * 32, 256, SM_TOT>>>(value, energy, conv_w, score_w);
    softmax_kernel<<<BB, 256>>>(out_align);
    context_kernel<<<dim3(BB, DD / 128, SS / 256), 128>>>(value, out_align,
                                                          out_ctx);
}

// round 10
// speedup vs baseline: 1.5119x; 1.0869x over previous
#include <cuda_runtime.h>
#include <cuda_fp16.h>
#include <cstdint>

// ============================================================================
// LocationAwareAttention  B=32, S=2048, D=512   (family-common PTX only:
// mma.sync.m16n8k16.f16 + ldmatrix + cp.async — NO tcgen05, target is sm_103)
//
// R10: warp-autonomous scores pipeline. Evidence (R5/R6/R8): tensor pinned at
// 37.9% and invariant to warps/CTAs/A-path -> the per-chunk __syncthreads
// phase-locks all warps (ldsm crossbar storms alternate with mma bursts).
// Fix: A (64x512) loaded to smem ONCE (one barrier); B tile is warp-private
// (each warp reads only its 64 n-rows) -> per-warp cp.async rings, per-warp
// wait_group, __syncwarp. ZERO block barriers in the K loop.
// Periphery = R9-proven (33us).
// Output: d_out = [ctx (B*D) | align (B*S)] fp32
// ============================================================================

#define BB 32
#define SS 2048
#define DD 512

__device__ __half g_wvt[DD * DD];     // w_v^T [n][k] fp16
__device__ float  g_qw[BB * DD];      // q@w_q + bias + conv_b  (atomic-built)
__device__ float  g_scores[BB * SS];

// ---------------- SMEM layout (bytes) ----------------
// A: 8 chunks x (64x64 fp16 tile, swizzled) = 64KB at offset 0.
// B: 8 warps x 2 stages x 8KB = 128KB.
#define SM_A    0
#define SM_B    65536
#define SM_QWB  196608
#define SM_CW0  198656
#define SM_CW1  200704
#define SM_CW2  202752
#define SM_SW   204800
#define SM_E0   206848
#define SM_E1   207104
#define SM_E2   207360
#define SM_RED  207616                 // 64 x 8 f32
#define SM_TOT  209664

// ---------------- PTX helpers ----------------
__device__ __forceinline__ uint32_t s2u(const void* p) {
    uint32_t a;
    asm("{ .reg .u64 t; cvta.to.shared.u64 t, %1; cvt.u32.u64 %0, t; }"
        : "=r"(a) : "l"(p));
    return a;
}
__device__ __forceinline__ void cp16(uint32_t dst, const void* src) {
    asm volatile("cp.async.ca.shared.global [%0], [%1], 16;"
                 :: "r"(dst), "l"(src) : "memory");
}
__device__ __forceinline__ void cp_commit() {
    asm volatile("cp.async.commit_group;" ::: "memory");
}
__device__ __forceinline__ void cp_wait0() {
    asm volatile("cp.async.wait_group 0;" ::: "memory");
}
__device__ __forceinline__ void cp_wait1() {
    asm volatile("cp.async.wait_group 1;" ::: "memory");
}
__device__ __forceinline__ void ldsm4(uint32_t& r0, uint32_t& r1,
                                      uint32_t& r2, uint32_t& r3, uint32_t a) {
    asm volatile("ldmatrix.sync.aligned.m8n8.x4.shared.b16 {%0,%1,%2,%3}, [%4];"
                 : "=r"(r0), "=r"(r1), "=r"(r2), "=r"(r3) : "r"(a));
}
__device__ __forceinline__ void mma16816(float* d, const uint32_t* a,
                                         const uint32_t* b) {
    asm volatile(
        "mma.sync.aligned.m16n8k16.row.col.f32.f16.f16.f32 "
        "{%0,%1,%2,%3}, {%4,%5,%6,%7}, {%8,%9}, {%0,%1,%2,%3};"
        : "+f"(d[0]), "+f"(d[1]), "+f"(d[2]), "+f"(d[3])
        : "r"(a[0]), "r"(a[1]), "r"(a[2]), "r"(a[3]), "r"(b[0]), "r"(b[1]));
}
__device__ __forceinline__ uint32_t packh(__half a, __half b) {
    __half2 h2; h2.x = a; h2.y = b;
    return *(uint32_t*)&h2;
}
__device__ __forceinline__ uint32_t swz(uint32_t row, uint32_t colByte) {
    return row * 128u + (colByte ^ ((row & 7u) << 4));
}

// ============================================================================
// zero: g_qw and ctx (both BB*DD) — must precede prep's atomics.
// ============================================================================
__global__ void zero_kernel(float* __restrict__ ctx) {
    int i = blockIdx.x * blockDim.x + threadIdx.x;
    if (i < BB * DD) { ctx[i] = 0.f; g_qw[i] = 0.f; }
}

// ============================================================================
// prep (R9-proven): 576 blocks x 256 threads.
//   [0,64):   w_v^T -> fp16 coalesced 64x64 smem-tile transpose
//   [64,576): qw k-split (8-way) + atomicAdd
// ============================================================================
__global__ void __launch_bounds__(256)
prep_kernel(const float* __restrict__ w_v,
            const float* __restrict__ query,
            const float* __restrict__ w_q,
            const float* __restrict__ bias,
            const float* __restrict__ conv_b) {
    const int blk = blockIdx.x, tid = threadIdx.x;
    if (blk < 64) {
        __shared__ float tile[64][65];
        const int ti = blk >> 3, tj = blk & 7;
#pragma unroll
        for (int q = 0; q < 4; ++q) {
            int idx = q * 256 + tid;
            int r = idx >> 4, c4 = idx & 15;
            float4 v = *(const float4*)(w_v + (size_t)(ti * 64 + r) * DD
                                        + tj * 64 + c4 * 4);
            tile[r][c4 * 4 + 0] = v.x;
            tile[r][c4 * 4 + 1] = v.y;
            tile[r][c4 * 4 + 2] = v.z;
            tile[r][c4 * 4 + 3] = v.w;
        }
        __syncthreads();
#pragma unroll
        for (int q = 0; q < 8; ++q) {
            int slot = q * 256 + tid;
            int nr = slot >> 5, kc = slot & 31;
            __half2 h = __floats2half2_rn(tile[kc * 2][nr],
                                          tile[kc * 2 + 1][nr]);
            *(__half2*)(g_wvt + (size_t)(tj * 64 + nr) * DD + ti * 64 + kc * 2) = h;
        }
    } else {
        const int bb = blk - 64;
        const int ks = bb & 7;
        const int dh = (bb >> 3) & 1;
        const int b  = bb >> 4;
        const int d  = dh * 256 + tid;
        const float* q = query + b * DD + ks * 64;
        const float* w = w_q + (size_t)(ks * 64) * DD + d;
        float a0 = 0.f, a1 = 0.f, a2 = 0.f, a3 = 0.f;
        float a4 = 0.f, a5 = 0.f, a6 = 0.f, a7 = 0.f;
#pragma unroll
        for (int k = 0; k < 64; k += 8) {
            a0 = fmaf(__ldg(q + k),     __ldg(w + (size_t)(k)     * DD), a0);
            a1 = fmaf(__ldg(q + k + 1), __ldg(w + (size_t)(k + 1) * DD), a1);
            a2 = fmaf(__ldg(q + k + 2), __ldg(w + (size_t)(k + 2) * DD), a2);
            a3 = fmaf(__ldg(q + k + 3), __ldg(w + (size_t)(k + 3) * DD), a3);
            a4 = fmaf(__ldg(q + k + 4), __ldg(w + (size_t)(k + 4) * DD), a4);
            a5 = fmaf(__ldg(q + k + 5), __ldg(w + (size_t)(k + 5) * DD), a5);
            a6 = fmaf(__ldg(q + k + 6), __ldg(w + (size_t)(k + 6) * DD), a6);
            a7 = fmaf(__ldg(q + k + 7), __ldg(w + (size_t)(k + 7) * DD), a7);
        }
        float sum = ((a0 + a1) + (a2 + a3)) + ((a4 + a5) + (a6 + a7));
        if (ks == 0) sum += bias[d] + conv_b[d];
        atomicAdd(&g_qw[b * DD + d], sum);
    }
}

// ============================================================================
// scores: block tile M=64 x N=512, K=512. 256 threads / 8 warps, warp tile
// 64x64. A in smem once; per-warp autonomous B pipelines (no block barriers
// in the K loop).
// ============================================================================
__global__ void __launch_bounds__(256, 1)
scores_kernel(const float* __restrict__ value,
              const float* __restrict__ energy,
              const float* __restrict__ conv_w,
              const float* __restrict__ score_w) {
    extern __shared__ char smem[];
    const uint32_t sb = s2u(smem);
    const int tid = threadIdx.x, wid = tid >> 5, lid = tid & 31;
    const int b = blockIdx.x >> 5, tile = blockIdx.x & 31;
    const int s0 = tile * 64;
    const size_t grow0 = (size_t)b * SS + s0;
    const int nwb = wid * 64;

    // ---- per-warp B pipeline: warp w loads its own 64 n-rows, 2-stage ----
    auto cpB = [&](int ch) {
        const int kb = ch * 64;
        const uint32_t bbuf = sb + SM_B
                            + (uint32_t)((wid << 1) + (ch & 1)) * 8192u;
#pragma unroll
        for (int q = 0; q < 16; ++q) {
            int t = lid + q * 32, n = t >> 3, c = t & 7;
            cp16(bbuf + swz((uint32_t)n, (uint32_t)c * 16),
                 g_wvt + (size_t)(nwb + n) * DD + kb + c * 8);
        }
        cp_commit();
    };

    // kick off the first two B transfers before the (heavier) A load
    cpB(0);
    cpB(1);

    // ---- epilogue constants ----
    float* c_qwb = (float*)(smem + SM_QWB);
    float* c_cw0 = (float*)(smem + SM_CW0);
    float* c_cw1 = (float*)(smem + SM_CW1);
    float* c_cw2 = (float*)(smem + SM_CW2);
    float* c_sw  = (float*)(smem + SM_SW);
    for (int d = tid; d < DD; d += 256) {
        c_qwb[d] = g_qw[b * DD + d];
        c_cw0[d] = conv_w[d * 3 + 0];
        c_cw1[d] = conv_w[d * 3 + 1];
        c_cw2[d] = conv_w[d * 3 + 2];
        c_sw[d]  = score_w[d];
    }
    if (tid < 64) {
        int s = s0 + tid, gs = b * SS + s;
        ((float*)(smem + SM_E1))[tid] = energy[gs];
        ((float*)(smem + SM_E0))[tid] = (s > 0)      ? energy[gs - 1] : 0.f;
        ((float*)(smem + SM_E2))[tid] = (s < SS - 1) ? energy[gs + 1] : 0.f;
    }

    // ---- A: all 8 chunks (64 x 512 fp32 -> fp16, swizzled 64x64 tiles) ----
#pragma unroll
    for (int ch = 0; ch < 8; ++ch) {
        const int kb = ch * 64;
        char* ah = smem + SM_A + ch * 8192;
#pragma unroll
        for (int q = 0; q < 2; ++q) {
            int t = tid * 2 + q, r = t >> 3, c = t & 7;
            const float4* src =
                (const float4*)(value + (grow0 + r) * DD + kb + c * 8);
            float4 v0 = src[0], v1 = src[1];
            uint4 hh;
            hh.x = packh(__float2half_rn(v0.x), __float2half_rn(v0.y));
            hh.y = packh(__float2half_rn(v0.z), __float2half_rn(v0.w));
            hh.z = packh(__float2half_rn(v1.x), __float2half_rn(v1.y));
            hh.w = packh(__float2half_rn(v1.z), __float2half_rn(v1.w));
            *(uint4*)(ah + swz((uint32_t)r, (uint32_t)c * 16)) = hh;
        }
    }
    __syncthreads();   // the ONLY block barrier before the epilogue

    float acc[4][8][4];
#pragma unroll
    for (int i = 0; i < 4; ++i)
#pragma unroll
        for (int j = 0; j < 8; ++j)
#pragma unroll
            for (int c = 0; c < 4; ++c) acc[i][j][c] = 0.f;

    auto compute = [&](int ch) {
        const uint32_t abuf = sb + SM_A + (uint32_t)ch * 8192u;
        const uint32_t bbuf = sb + SM_B
                            + (uint32_t)((wid << 1) + (ch & 1)) * 8192u;
#pragma unroll
        for (int s = 0; s < 4; ++s) {
            uint32_t bfr[8][2];
#pragma unroll
            for (int np = 0; np < 4; ++np) {
                uint32_t row = np * 16 + ((lid & 16) >> 1) + (lid & 7);
                uint32_t col = s * 32 + ((lid & 8) << 1);
                ldsm4(bfr[np * 2][0], bfr[np * 2][1],
                      bfr[np * 2 + 1][0], bfr[np * 2 + 1][1],
                      bbuf + swz(row, col));
            }
#pragma unroll
            for (int mi = 0; mi < 4; ++mi) {
                uint32_t row = mi * 16 + (lid & 15);
                uint32_t col = s * 32 + (lid & 16);
                uint32_t ah[4];
                ldsm4(ah[0], ah[1], ah[2], ah[3], abuf + swz(row, col));
#pragma unroll
                for (int ni = 0; ni < 8; ++ni)
                    mma16816(acc[mi][ni], ah, bfr[ni]);
            }
        }
    };

    // ---- warp-autonomous K loop: no block barriers ----
    for (int ch = 0; ch < 8; ++ch) {
        if (ch < 7) cp_wait1();   // this warp's group(ch) complete
        else        cp_wait0();
        __syncwarp();             // make cp.async data warp-visible
        compute(ch);              // reads stage ch&1
        if (ch < 6) cpB(ch + 2);  // refill stage ch&1 (just freed)
    }

    // ---- epilogue ----
    const float* E0 = (const float*)(smem + SM_E0);
    const float* E1 = (const float*)(smem + SM_E1);
    const float* E2 = (const float*)(smem + SM_E2);
    float e0r[8], e1r[8], e2r[8];
#pragma unroll
    for (int mi = 0; mi < 4; ++mi)
#pragma unroll
        for (int h = 0; h < 2; ++h) {
            int r = mi * 16 + h * 8 + (lid >> 2);
            e0r[mi * 2 + h] = E0[r];
            e1r[mi * 2 + h] = E1[r];
            e2r[mi * 2 + h] = E2[r];
        }
    float part[8];
#pragma unroll
    for (int i = 0; i < 8; ++i) part[i] = 0.f;

#pragma unroll
    for (int ni = 0; ni < 8; ++ni) {
        int d0 = nwb + ni * 8 + 2 * (lid & 3);
        float qb0 = c_qwb[d0], qb1 = c_qwb[d0 + 1];
        float w00 = c_cw0[d0], w01 = c_cw0[d0 + 1];
        float w10 = c_cw1[d0], w11 = c_cw1[d0 + 1];
        float w20 = c_cw2[d0], w21 = c_cw2[d0 + 1];
        float sw0 = c_sw[d0],  sw1 = c_sw[d0 + 1];
#pragma unroll
        for (int mi = 0; mi < 4; ++mi)
#pragma unroll
            for (int h = 0; h < 2; ++h) {
                int pi = mi * 2 + h;
                float x0 = acc[mi][ni][h * 2] + qb0
                         + e0r[pi] * w00 + e1r[pi] * w10 + e2r[pi] * w20;
                float x1 = acc[mi][ni][h * 2 + 1] + qb1
                         + e0r[pi] * w01 + e1r[pi] * w11 + e2r[pi] * w21;
                float t0 = 1.f - __fdividef(2.f, __expf(2.f * x0) + 1.f);
                float t1 = 1.f - __fdividef(2.f, __expf(2.f * x1) + 1.f);
                part[pi] = fmaf(t0, sw0, fmaf(t1, sw1, part[pi]));
            }
    }
#pragma unroll
    for (int pi = 0; pi < 8; ++pi) {
        part[pi] += __shfl_xor_sync(0xffffffffu, part[pi], 1);
        part[pi] += __shfl_xor_sync(0xffffffffu, part[pi], 2);
    }
    float* red = (float*)(smem + SM_RED);
    if ((lid & 3) == 0) {
#pragma unroll
        for (int mi = 0; mi < 4; ++mi)
#pragma unroll
            for (int h = 0; h < 2; ++h) {
                int r = mi * 16 + h * 8 + (lid >> 2);
                red[r * 8 + wid] = part[mi * 2 + h];
            }
    }
    __syncthreads();
    if (tid < 64) {
        float sum = 0.f;   // score_b dropped: softmax shift-invariant
#pragma unroll
        for (int w = 0; w < 8; ++w) sum += red[tid * 8 + w];
        g_scores[b * SS + s0 + tid] = sum;
    }
}

// ============================================================================
// softmax per batch -> align  (proven 5us)
// ============================================================================
__global__ void softmax_kernel(float* __restrict__ align_out) {
    __shared__ float wred[8];
    int b = blockIdx.x, t = threadIdx.x, w = t >> 5, l = t & 31;
    const float4* s4 = (const float4*)(g_scores + b * SS);
    float4 v0 = s4[t];
    float4 v1 = s4[t + 256];
    float m = fmaxf(fmaxf(fmaxf(v0.x, v0.y), fmaxf(v0.z, v0.w)),
                    fmaxf(fmaxf(v1.x, v1.y), fmaxf(v1.z, v1.w)));
#pragma unroll
    for (int o = 16; o > 0; o >>= 1)
        m = fmaxf(m, __shfl_xor_sync(0xffffffffu, m, o));
    if (l == 0) wred[w] = m;
    __syncthreads();
    m = wred[0];
#pragma unroll
    for (int i = 1; i < 8; ++i) m = fmaxf(m, wred[i]);
    __syncthreads();

    float4 e0, e1;
    e0.x = __expf(v0.x - m); e0.y = __expf(v0.y - m);
    e0.z = __expf(v0.z - m); e0.w = __expf(v0.w - m);
    e1.x = __expf(v1.x - m); e1.y = __expf(v1.y - m);
    e1.z = __expf(v1.z - m); e1.w = __expf(v1.w - m);
    float sum = e0.x + e0.y + e0.z + e0.w + e1.x + e1.y + e1.z + e1.w;
#pragma unroll
    for (int o = 16; o > 0; o >>= 1)
        sum += __shfl_xor_sync(0xffffffffu, sum, o);
    if (l == 0) wred[w] = sum;
    __syncthreads();
    sum = wred[0];
#pragma unroll
    for (int i = 1; i < 8; ++i) sum += wred[i];
    float inv = 1.f / sum;
    e0.x *= inv; e0.y *= inv; e0.z *= inv; e0.w *= inv;
    e1.x *= inv; e1.y *= inv; e1.z *= inv; e1.w *= inv;
    float4* a4 = (float4*)(align_out + b * SS);
    a4[t] = e0;
    a4[t + 256] = e1;
}

// ============================================================================
// context: ctx[b,d] = sum_s align[b,s] * value[b,s,d]   (R4-proven)
// ============================================================================
__global__ void context_kernel(const float* __restrict__ value,
                               const float* __restrict__ align,
                               float* __restrict__ ctx) {
    int b = blockIdx.x, dch = blockIdx.y, sch = blockIdx.z;
    int d = dch * 128 + threadIdx.x;
    const float* vb = value + ((size_t)b * SS + sch * 256) * DD + d;
    const float* ab = align + b * SS + sch * 256;
    float acc = 0.f;
#pragma unroll 8
    for (int s = 0; s < 256; ++s)
        acc = fmaf(ab[s], vb[(size_t)s * DD], acc);
    atomicAdd(&ctx[b * DD + d], acc);
}

// ============================================================================
// launch
// ============================================================================
extern "C" void kernel_launch(void* const* d_in, const int* in_sizes, int n_in,
                              void* d_out, int out_size) {
    const float* query   = (const float*)d_in[0];
    const float* value   = (const float*)d_in[1];
    const float* energy  = (const float*)d_in[2];
    const float* conv_w  = (const float*)d_in[3];
    const float* conv_b  = (const float*)d_in[4];
    const float* w_q     = (const float*)d_in[5];
    const float* w_v     = (const float*)d_in[6];
    const float* bias    = (const float*)d_in[7];
    const float* score_w = (const float*)d_in[8];
    float* out_ctx   = (float*)d_out;            // [B*D]
    float* out_align = (float*)d_out + BB * DD;  // [B*S]

    cudaFuncSetAttribute(scores_kernel,
                         cudaFuncAttributeMaxDynamicSharedMemorySize, SM_TOT);

    zero_kernel<<<(BB * DD + 255) / 256, 256>>>(out_ctx);
    prep_kernel<<<576, 256>>>(w_v, query, w_q, bias, conv_b);
    scores_kernel<<<BB * 32, 256, SM_TOT>>>(value, energy, conv_w, score_w);
    softmax_kernel<<<BB, 256>>>(out_align);
    context_kernel<<<dim3(BB, DD / 128, SS / 256), 128>>>(value, out_align,
                                                          out_ctx);
}